// round 14
// baseline (speedup 1.0000x reference)
#include <cuda_runtime.h>
#include <cuda_fp16.h>
#include <cstdint>

// ---------------------------------------------------------------------------
// Problem constants
// ---------------------------------------------------------------------------
static constexpr long NR    = 32768;   // rows of x
static constexpr int  KD    = 2304;    // C_IN
static constexpr int  NF    = 2816;    // C_WITH_GATE
static constexpr int  SOUT  = 2304;    // SIZE_OUT
static constexpr int  NGATE = 512;     // NUM_GATES

static constexpr int TM  = 128;        // CTA tile M
static constexpr int TN  = 128;        // CTA tile N
static constexpr int KB  = 64;         // K per stage
static constexpr int NKB = KD / KB;    // 36 (divisible by 3)

static constexpr int A_BYTES = TM * KB * 2;        // 16 KB
static constexpr int STAGE   = 2 * A_BYTES;        // A + B = 32 KB
static constexpr int NSTG    = 3;
static constexpr int SMEM_BYTES = NSTG * STAGE;    // 98304 -> 2 CTAs/SM

static constexpr int MT_CNT      = (int)(NR / TM); // 256
static constexpr int GATE_TILES  = NGATE / TN;     // 4
static constexpr int FIELD_TILES = SOUT / TN;      // 18

static constexpr int XPREP_BIDS  = MT_CNT;                  // 256
static constexpr int WPREP_BIDS  = NF / 32;                 // 88
static constexpr int PREP_BIDS   = XPREP_BIDS + WPREP_BIDS; // 344
static constexpr int GATE_BIDS   = MT_CNT * GATE_TILES;     // 1024
static constexpr int FIELD_BIDS  = MT_CNT * FIELD_TILES;    // 4608
static constexpr int GATE0       = PREP_BIDS;               // 344
static constexpr int FIELD0      = GATE0 + GATE_BIDS;       // 1368
static constexpr int TOTAL_BIDS  = FIELD0 + FIELD_BIDS;     // 5976

// ---------------------------------------------------------------------------
// Scratch (device globals; no runtime allocation)
// ---------------------------------------------------------------------------
__device__ __half g_xh[NR * KD];                // x in fp16
__device__ __half g_wt[(long)NF * KD];          // W^T in fp16: [NF, KD]
__device__ float  g_gates[NR * NGATE];          // sigmoid(gate feats)
__device__ unsigned g_done[MT_CNT];             // gate tiles done per mt
__device__ unsigned g_xready[MT_CNT];           // x rows converted per mt
__device__ unsigned g_wdone;                    // W strips transposed

// ---------------------------------------------------------------------------
// Helpers (baseline compute_103: cp.async / ldmatrix / mma.sync)
// ---------------------------------------------------------------------------
__device__ __forceinline__ uint32_t smem_u32(const void* p) {
    uint32_t a;
    asm("{ .reg .u64 t; cvta.to.shared.u64 t, %1; cvt.u32.u64 %0, t; }"
        : "=r"(a) : "l"(p));
    return a;
}

__device__ __forceinline__ uint32_t swz(uint32_t o) {
    return o ^ ((o >> 3) & 0x70);   // SW128 (Swizzle<3,4,3>)
}

__device__ __forceinline__ void cp16(uint32_t dst, const void* src) {
    asm volatile("cp.async.cg.shared.global [%0], [%1], 16;"
                 :: "r"(dst), "l"(src));
}

__device__ __forceinline__ void ldsm4(uint32_t* r, uint32_t a) {
    asm volatile("ldmatrix.sync.aligned.m8n8.x4.shared.b16 {%0,%1,%2,%3}, [%4];"
                 : "=r"(r[0]), "=r"(r[1]), "=r"(r[2]), "=r"(r[3]) : "r"(a));
}

__device__ __forceinline__ void mma16816(float* c, const uint32_t* a,
                                         const uint32_t* b) {
    asm volatile(
        "mma.sync.aligned.m16n8k16.row.col.f32.f16.f16.f32 "
        "{%0,%1,%2,%3}, {%4,%5,%6,%7}, {%8,%9}, {%0,%1,%2,%3};"
        : "+f"(c[0]), "+f"(c[1]), "+f"(c[2]), "+f"(c[3])
        : "r"(a[0]), "r"(a[1]), "r"(a[2]), "r"(a[3]), "r"(b[0]), "r"(b[1]));
}

__device__ __forceinline__ float sigf(float v) {
    return 1.0f / (1.0f + __expf(-v));
}

// ---------------------------------------------------------------------------
// Kernel 0: reset dependency flags (graph-replay determinism)
// ---------------------------------------------------------------------------
__global__ void init_kernel() {
    g_done[threadIdx.x] = 0;
    g_xready[threadIdx.x] = 0;
    if (threadIdx.x == 0) g_wdone = 0;
}

// ---------------------------------------------------------------------------
// Mega kernel: prep + gates + fields in ONE launch, flag-ordered.
// ---------------------------------------------------------------------------
__device__ __forceinline__ void load_stage(uint32_t sb, int buf,
                                           const __half* __restrict__ A,
                                           const __half* __restrict__ B,
                                           int k0, int tid) {
    const int r = tid >> 3, j = tid & 7;            // r: 0..15
    const uint32_t d0 = sb + buf * STAGE + swz((uint32_t)(r * 128 + j * 16));
    const long s0 = (long)r * KD + k0 + j * 8;
#pragma unroll
    for (int i = 0; i < 8; i++) {                   // rows r + 16*i
        uint32_t d = d0 + i * 2048;                 // +16 rows (swz invariant)
        long s = s0 + (long)i * 16 * KD;
        cp16(d, A + s);
        cp16(d + A_BYTES, B + s);
    }
}

struct Frag {
    uint32_t row_a[4];
    uint32_t xor_a;
    uint32_t row_b[4];
    uint32_t xor_b[4];
};

// One K-block on compile-time stage BUF, prefetching stage LBUF (4 cp16/ks).
template <int BUF, int LBUF>
__device__ __forceinline__ void kblock(uint32_t sb, const Frag& fr,
                                       float c[4][8][4], int ajs, int bjs,
                                       uint32_t d_pre,
                                       const __half* __restrict__ As,
                                       const __half* __restrict__ Bs,
                                       bool do_load) {
    const uint32_t baseA = sb + BUF * STAGE;
    const uint32_t baseB = baseA + A_BYTES;
    const uint32_t ld = sb + LBUF * STAGE + d_pre;
#pragma unroll
    for (int ks = 0; ks < 4; ks++) {
        const uint32_t kca = (uint32_t)((2 * ks + ajs) * 16);
        const uint32_t kcb = (uint32_t)((2 * ks + bjs) * 16);
        uint32_t a[4][4], b[4][4];
        ldsm4(b[0], baseB + fr.row_b[0] + (kcb ^ fr.xor_b[0]));
        ldsm4(a[0], baseA + fr.row_a[0] + (kca ^ fr.xor_a));
        ldsm4(b[1], baseB + fr.row_b[1] + (kcb ^ fr.xor_b[1]));
        ldsm4(a[1], baseA + fr.row_a[1] + (kca ^ fr.xor_a));
        ldsm4(b[2], baseB + fr.row_b[2] + (kcb ^ fr.xor_b[2]));
        ldsm4(a[2], baseA + fr.row_a[2] + (kca ^ fr.xor_a));
        ldsm4(b[3], baseB + fr.row_b[3] + (kcb ^ fr.xor_b[3]));
        ldsm4(a[3], baseA + fr.row_a[3] + (kca ^ fr.xor_a));
        if (do_load) {
            cp16(ld + (2 * ks) * 2048, As + (long)(2 * ks) * 16 * KD);
            cp16(ld + (2 * ks + 1) * 2048, As + (long)(2 * ks + 1) * 16 * KD);
            cp16(ld + A_BYTES + (2 * ks) * 2048,
                 Bs + (long)(2 * ks) * 16 * KD);
            cp16(ld + A_BYTES + (2 * ks + 1) * 2048,
                 Bs + (long)(2 * ks + 1) * 16 * KD);
        }
#pragma unroll
        for (int mi = 0; mi < 4; mi++)
#pragma unroll
            for (int pi = 0; pi < 4; pi++) {
                mma16816(c[mi][2 * pi],     a[mi], &b[pi][0]);
                mma16816(c[mi][2 * pi + 1], a[mi], &b[pi][2]);
            }
    }
}

__global__ void __launch_bounds__(128, 2) mega_kernel(
    const float* __restrict__ x, const float* __restrict__ W,
    float* __restrict__ out) {
    extern __shared__ __align__(1024) unsigned char smem_raw[];
    const int tid = threadIdx.x;
    const int bid = blockIdx.x;

    // ---------------- x-prep: convert 128 rows of x to fp16 ----------------
    if (bid < XPREP_BIDS) {
        const int mt = bid;
        const float4* src =
            reinterpret_cast<const float4*>(x) + (long)mt * TM * (KD / 4);
        __half2* dst = reinterpret_cast<__half2*>(g_xh + (long)mt * TM * KD);
#pragma unroll 8
        for (int i = tid; i < TM * (KD / 4); i += 128) {
            float4 v = src[i];
            dst[2 * i]     = __floats2half2_rn(v.x, v.y);
            dst[2 * i + 1] = __floats2half2_rn(v.z, v.w);
        }
        __syncthreads();
        if (tid == 0) {
            __threadfence();
            atomicExch(&g_xready[mt], 1u);
        }
        return;
    }

    // ---------------- W-prep: transpose a 32-col strip of W ----------------
    if (bid < PREP_BIDS) {
        float (*t)[33] = reinterpret_cast<float (*)[33]>(smem_raw);
        const int n0 = (bid - XPREP_BIDS) * 32;
        const int tx = tid & 31, ty = tid >> 5;   // 32 x 4
        for (int k0 = 0; k0 < KD; k0 += 32) {
#pragma unroll
            for (int i = 0; i < 32; i += 4)
                t[ty + i][tx] = W[(long)(k0 + ty + i) * NF + n0 + tx];
            __syncthreads();
#pragma unroll
            for (int i = 0; i < 32; i += 4)
                g_wt[(long)(n0 + ty + i) * KD + k0 + tx] =
                    __float2half_rn(t[tx][ty + i]);
            __syncthreads();
        }
        if (tid == 0) {
            __threadfence();
            atomicAdd(&g_wdone, 1u);
        }
        return;
    }

    // ---------------- GEMM tiles ----------------
    const uint32_t sb = smem_u32(smem_raw);
    const int lane = tid & 31, wid = tid >> 5;

    int mt, nt, n_off, mode;
    if (bid < FIELD0) {             // gate tiles, nt fastest
        int g = bid - GATE0;
        mt = g >> 2;                // GATE_TILES = 4
        nt = g & 3;
        n_off = SOUT + nt * TN;
        mode = 0;
    } else {                        // field tiles, nt FASTEST (L2 A-reuse)
        int f = bid - FIELD0;
        mt = f / FIELD_TILES;
        nt = f - mt * FIELD_TILES;
        n_off = nt * TN;
        mode = 1;
    }

    // wait until inputs for this tile are converted
    if (tid == 0) {
        while (*(volatile unsigned*)&g_xready[mt] == 0u) { }
        while (*(volatile unsigned*)&g_wdone < (unsigned)WPREP_BIDS) { }
    }
    __syncthreads();
    __threadfence();                // acquire side

    const __half* A = g_xh + (long)mt * TM * KD;
    const __half* B = g_wt + (long)n_off * KD;

    const int wm = wid & 1, wn = wid >> 1;   // 2 x 2 warp grid
    const int m0 = wm * 64, n0 = wn * 64;

    const int arow = (lane & 7) + ((lane >> 3) & 1) * 8;  // 0..15 within m16
    const int ajs  = lane >> 4;                           // k-half 0/1
    const int brow = (lane & 7) + (lane >> 4) * 8;        // 0..15 within n16
    const int bjs  = (lane >> 3) & 1;                     // k-half 0/1

    Frag fr;
#pragma unroll
    for (int mi = 0; mi < 4; mi++)
        fr.row_a[mi] = (uint32_t)((m0 + mi * 16 + arow) * 128);
    fr.xor_a = (uint32_t)((arow & 7) * 16);
#pragma unroll
    for (int pi = 0; pi < 4; pi++) {
        int row = n0 + pi * 16 + brow;
        fr.row_b[pi] = (uint32_t)(row * 128);
        fr.xor_b[pi] = (uint32_t)((row & 7) * 16);
    }

    const int lr = tid >> 3, lj = tid & 7;
    const uint32_t d_pre = swz((uint32_t)(lr * 128 + lj * 16));
    const long s0 = (long)lr * KD + lj * 8;

    float c[4][8][4];
#pragma unroll
    for (int mi = 0; mi < 4; mi++)
#pragma unroll
        for (int ni = 0; ni < 8; ni++)
#pragma unroll
            for (int q = 0; q < 4; q++) c[mi][ni][q] = 0.f;

    load_stage(sb, 0, A, B, 0, tid);
    asm volatile("cp.async.commit_group;" ::: "memory");
    load_stage(sb, 1, A, B, KB, tid);
    asm volatile("cp.async.commit_group;" ::: "memory");

    for (int kb0 = 0; kb0 < NKB; kb0 += 3) {
#pragma unroll
        for (int u = 0; u < 3; u++) {
            const int kb = kb0 + u;
            asm volatile("cp.async.wait_group 1;" ::: "memory");
            __syncthreads();
            const bool dl = (kb + 2 < NKB);
            const __half* As = A + s0 + (long)(kb + 2) * KB;
            const __half* Bs = B + s0 + (long)(kb + 2) * KB;
            if (u == 0)
                kblock<0, 2>(sb, fr, c, ajs, bjs, d_pre, As, Bs, dl);
            else if (u == 1)
                kblock<1, 0>(sb, fr, c, ajs, bjs, d_pre, As, Bs, dl);
            else
                kblock<2, 1>(sb, fr, c, ajs, bjs, d_pre, As, Bs, dl);
            asm volatile("cp.async.commit_group;" ::: "memory");
        }
    }

    // ----- fused epilogue -----
    const long gm = (long)mt * TM + m0;
    const int rr = lane >> 2, cc = (lane & 3) * 2;

    if (mode == 0) {
        const int gn = nt * TN + n0;
#pragma unroll
        for (int mi = 0; mi < 4; mi++)
#pragma unroll
            for (int ni = 0; ni < 8; ni++) {
                long r0 = gm + mi * 16 + rr;
                int col = gn + ni * 8 + cc;
                *reinterpret_cast<float2*>(&g_gates[r0 * NGATE + col]) =
                    make_float2(sigf(c[mi][ni][0]), sigf(c[mi][ni][1]));
                *reinterpret_cast<float2*>(&g_gates[(r0 + 8) * NGATE + col]) =
                    make_float2(sigf(c[mi][ni][2]), sigf(c[mi][ni][3]));
            }
        __syncthreads();
        __threadfence();
        if (tid == 0) atomicAdd(&g_done[mt], 1u);
    } else {
        if (tid == 0) {
            while (*(volatile unsigned*)&g_done[mt] < (unsigned)GATE_TILES) { }
        }
        __syncthreads();
        __threadfence();

        const int gn = nt * TN + n0;
#pragma unroll
        for (int mi = 0; mi < 4; mi++)
#pragma unroll
            for (int ni = 0; ni < 8; ni++) {
                int col = gn + ni * 8 + cc;
                int gi0, gi1;
                if (col < 256)       { gi0 = gi1 = -1; }
                else if (col < 1024) { gi0 = (col - 256) / 3;
                                       gi1 = (col + 1 - 256) / 3; }
                else                 { gi0 = 256 + (col - 1024) / 5;
                                       gi1 = 256 + (col + 1 - 1024) / 5; }
#pragma unroll
                for (int h = 0; h < 2; h++) {
                    long r0 = gm + mi * 16 + rr + h * 8;
                    float f0 = c[mi][ni][2 * h], f1 = c[mi][ni][2 * h + 1];
                    float o0, o1;
                    if (col < 256) {
                        o0 = f0 * sigf(f0);
                        o1 = f1 * sigf(f1);
                    } else {
                        const float* grow = g_gates + r0 * NGATE;
                        o0 = f0 * grow[gi0];
                        o1 = f1 * grow[gi1];
                    }
                    *reinterpret_cast<float2*>(&out[r0 * SOUT + col]) =
                        make_float2(o0, o1);
                }
            }
    }
}

// ---------------------------------------------------------------------------
extern "C" void kernel_launch(void* const* d_in, const int* in_sizes, int n_in,
                              void* d_out, int out_size) {
    const float* x = (const float*)d_in[0];
    const float* W = (const float*)d_in[1];
    float* out = (float*)d_out;

    init_kernel<<<1, 256>>>();

    cudaFuncSetAttribute(mega_kernel,
                         cudaFuncAttributeMaxDynamicSharedMemorySize,
                         SMEM_BYTES);
    mega_kernel<<<TOTAL_BIDS, 128, SMEM_BYTES>>>(x, W, out);
}

// round 15
// speedup vs baseline: 1.0629x; 1.0629x over previous
#include <cuda_runtime.h>
#include <cuda_fp16.h>
#include <cstdint>

// ---------------------------------------------------------------------------
// Problem constants
// ---------------------------------------------------------------------------
static constexpr long NR    = 32768;   // rows of x
static constexpr int  KD    = 2304;    // C_IN
static constexpr int  NF    = 2816;    // C_WITH_GATE
static constexpr int  SOUT  = 2304;    // SIZE_OUT
static constexpr int  NGATE = 512;     // NUM_GATES

static constexpr int TM  = 128;        // CTA tile M
static constexpr int TN  = 128;        // CTA tile N
static constexpr int KB  = 64;         // K per stage
static constexpr int NKB = KD / KB;    // 36 (divisible by 3)

static constexpr int A_BYTES = TM * KB * 2;        // 16 KB
static constexpr int STAGE   = 2 * A_BYTES;        // A + B = 32 KB
static constexpr int NSTG    = 3;
static constexpr int SMEM_BYTES = NSTG * STAGE;    // 98304 -> 2 CTAs/SM

static constexpr int MT_CNT      = (int)(NR / TM); // 256
static constexpr int GATE_TILES  = NGATE / TN;     // 4
static constexpr int FIELD_TILES = SOUT / TN;      // 18
static constexpr int GATE_BIDS   = MT_CNT * GATE_TILES;     // 1024
static constexpr int FIELD_BIDS  = MT_CNT * FIELD_TILES;    // 4608
static constexpr int TOTAL_BIDS  = GATE_BIDS + FIELD_BIDS;  // 5632

static constexpr int NUM_SMS     = 160;            // >= 148/152, safe bound
static constexpr unsigned STAGGER_CYC = 1400;      // ~half a kb period

// ---------------------------------------------------------------------------
// Scratch (device globals; no runtime allocation)
// ---------------------------------------------------------------------------
__device__ __half g_xh[NR * KD];                // x in fp16
__device__ __half g_wt[(long)NF * KD];          // W^T in fp16: [NF, KD]
__device__ float  g_gates[NR * NGATE];          // sigmoid(gate feats)
__device__ unsigned g_done[MT_CNT];             // gate tiles done per mt
__device__ unsigned g_smslot[NUM_SMS];          // CTA arrival count per SM

// ---------------------------------------------------------------------------
// Helpers (baseline compute_103: cp.async / ldmatrix / mma.sync)
// ---------------------------------------------------------------------------
__device__ __forceinline__ uint32_t smem_u32(const void* p) {
    uint32_t a;
    asm("{ .reg .u64 t; cvta.to.shared.u64 t, %1; cvt.u32.u64 %0, t; }"
        : "=r"(a) : "l"(p));
    return a;
}

__device__ __forceinline__ uint32_t swz(uint32_t o) {
    return o ^ ((o >> 3) & 0x70);   // SW128 (Swizzle<3,4,3>)
}

__device__ __forceinline__ void cp16(uint32_t dst, const void* src) {
    asm volatile("cp.async.cg.shared.global [%0], [%1], 16;"
                 :: "r"(dst), "l"(src));
}

__device__ __forceinline__ void ldsm4(uint32_t* r, uint32_t a) {
    asm volatile("ldmatrix.sync.aligned.m8n8.x4.shared.b16 {%0,%1,%2,%3}, [%4];"
                 : "=r"(r[0]), "=r"(r[1]), "=r"(r[2]), "=r"(r[3]) : "r"(a));
}

__device__ __forceinline__ void mma16816(float* c, const uint32_t* a,
                                         const uint32_t* b) {
    asm volatile(
        "mma.sync.aligned.m16n8k16.row.col.f32.f16.f16.f32 "
        "{%0,%1,%2,%3}, {%4,%5,%6,%7}, {%8,%9}, {%0,%1,%2,%3};"
        : "+f"(c[0]), "+f"(c[1]), "+f"(c[2]), "+f"(c[3])
        : "r"(a[0]), "r"(a[1]), "r"(a[2]), "r"(a[3]), "r"(b[0]), "r"(b[1]));
}

__device__ __forceinline__ float sigf(float v) {
    return 1.0f / (1.0f + __expf(-v));
}

// ---------------------------------------------------------------------------
// Kernel 1: x (fp32) -> fp16 ; block 0 also resets flags
// ---------------------------------------------------------------------------
__global__ void split_x_kernel(const float4* __restrict__ x) {
    if (blockIdx.x == 0) {
        g_done[threadIdx.x] = 0;                 // 256 threads = MT_CNT
        if (threadIdx.x < NUM_SMS) g_smslot[threadIdx.x] = 0;
    }
    long i = (long)blockIdx.x * 256 + threadIdx.x;
    if (i >= NR * KD / 4) return;
    float4 v = x[i];
    __half2* p = reinterpret_cast<__half2*>(g_xh) + 2 * i;
    p[0] = __floats2half2_rn(v.x, v.y);
    p[1] = __floats2half2_rn(v.z, v.w);
}

// ---------------------------------------------------------------------------
// Kernel 2: transpose W[K,NF] -> g_wt [NF,KD] fp16
// ---------------------------------------------------------------------------
__global__ void splitW_kernel(const float* __restrict__ W) {
    __shared__ float t[32][33];
    int n0 = blockIdx.x * 32, k0 = blockIdx.y * 32;
    int tx = threadIdx.x, ty = threadIdx.y;  // 32 x 8
#pragma unroll
    for (int i = 0; i < 32; i += 8)
        t[ty + i][tx] = W[(long)(k0 + ty + i) * NF + n0 + tx];
    __syncthreads();
#pragma unroll
    for (int i = 0; i < 32; i += 8)
        g_wt[(long)(n0 + ty + i) * KD + k0 + tx] = __float2half_rn(t[tx][ty + i]);
}

// ---------------------------------------------------------------------------
// Kernel 3: merged fp16 HMMA GEMM (gates + fields in ONE launch).
//   bid <  GATE_BIDS : gate tile  -> sigmoid -> g_gates, bump g_done[mt]
//   bid >= GATE_BIDS : field tile -> wait g_done[mt] -> silu/gate -> out
// Field tiles nt-FASTEST (L2 A-reuse). CTA 128x128, 4 warps (2x2, 64x64),
// 2 CTAs/SM, 3-stage cp.async with prefetch spread across ks groups.
// Anti-convoy: the 2nd CTA to land on each SM delays ~half a kb so the two
// co-resident CTAs hit their kb barriers out of phase (tensor pipe covered).
// ---------------------------------------------------------------------------
__device__ __forceinline__ void load_stage(uint32_t sb, int buf,
                                           const __half* __restrict__ A,
                                           const __half* __restrict__ B,
                                           int k0, int tid) {
    const int r = tid >> 3, j = tid & 7;            // r: 0..15
    const uint32_t d0 = sb + buf * STAGE + swz((uint32_t)(r * 128 + j * 16));
    const long s0 = (long)r * KD + k0 + j * 8;
#pragma unroll
    for (int i = 0; i < 8; i++) {                   // rows r + 16*i
        uint32_t d = d0 + i * 2048;                 // +16 rows (swz invariant)
        long s = s0 + (long)i * 16 * KD;
        cp16(d, A + s);
        cp16(d + A_BYTES, B + s);
    }
}

struct Frag {
    uint32_t row_a[4];   // (row*128) for A ldsm (m16 slices)
    uint32_t xor_a;
    uint32_t row_b[4];   // (row*128) for B ldsm (n16 slices)
    uint32_t xor_b[4];
};

// One K-block on compile-time stage BUF, prefetching stage LBUF (4 cp16/ks).
template <int BUF, int LBUF>
__device__ __forceinline__ void kblock(uint32_t sb, const Frag& fr,
                                       float c[4][8][4], int ajs, int bjs,
                                       uint32_t d_pre,
                                       const __half* __restrict__ As,
                                       const __half* __restrict__ Bs,
                                       bool do_load) {
    const uint32_t baseA = sb + BUF * STAGE;
    const uint32_t baseB = baseA + A_BYTES;
    const uint32_t ld = sb + LBUF * STAGE + d_pre;
#pragma unroll
    for (int ks = 0; ks < 4; ks++) {
        const uint32_t kca = (uint32_t)((2 * ks + ajs) * 16);
        const uint32_t kcb = (uint32_t)((2 * ks + bjs) * 16);
        uint32_t a[4][4], b[4][4];
        ldsm4(b[0], baseB + fr.row_b[0] + (kcb ^ fr.xor_b[0]));
        ldsm4(a[0], baseA + fr.row_a[0] + (kca ^ fr.xor_a));
        ldsm4(b[1], baseB + fr.row_b[1] + (kcb ^ fr.xor_b[1]));
        ldsm4(a[1], baseA + fr.row_a[1] + (kca ^ fr.xor_a));
        ldsm4(b[2], baseB + fr.row_b[2] + (kcb ^ fr.xor_b[2]));
        ldsm4(a[2], baseA + fr.row_a[2] + (kca ^ fr.xor_a));
        ldsm4(b[3], baseB + fr.row_b[3] + (kcb ^ fr.xor_b[3]));
        ldsm4(a[3], baseA + fr.row_a[3] + (kca ^ fr.xor_a));
        if (do_load) {
            cp16(ld + (2 * ks) * 2048, As + (long)(2 * ks) * 16 * KD);
            cp16(ld + (2 * ks + 1) * 2048, As + (long)(2 * ks + 1) * 16 * KD);
            cp16(ld + A_BYTES + (2 * ks) * 2048,
                 Bs + (long)(2 * ks) * 16 * KD);
            cp16(ld + A_BYTES + (2 * ks + 1) * 2048,
                 Bs + (long)(2 * ks + 1) * 16 * KD);
        }
#pragma unroll
        for (int mi = 0; mi < 4; mi++)
#pragma unroll
            for (int pi = 0; pi < 4; pi++) {
                mma16816(c[mi][2 * pi],     a[mi], &b[pi][0]);
                mma16816(c[mi][2 * pi + 1], a[mi], &b[pi][2]);
            }
    }
}

__global__ void __launch_bounds__(128, 2) gemm_kernel(float* __restrict__ out) {
    extern __shared__ __align__(1024) unsigned char smem_raw[];
    const uint32_t sb = smem_u32(smem_raw);
    const int tid = threadIdx.x, lane = tid & 31, wid = tid >> 5;
    const int bid = blockIdx.x;

    // ---- anti-convoy stagger: 2nd CTA arriving on this SM delays ----
    __shared__ unsigned s_slot;
    if (tid == 0) {
        uint32_t smid;
        asm("mov.u32 %0, %%smid;" : "=r"(smid));
        s_slot = atomicAdd(&g_smslot[smid], 1u);
    }
    __syncthreads();
    if (s_slot == 1u) {
        unsigned long long t0 = clock64();
        while ((unsigned long long)(clock64() - t0) < STAGGER_CYC) { }
    }

    int mt, nt, n_off, mode;
    if (bid < GATE_BIDS) {          // gate tiles first, nt fastest
        mt = bid >> 2;              // GATE_TILES = 4
        nt = bid & 3;
        n_off = SOUT + nt * TN;
        mode = 0;
    } else {                        // field tiles, nt FASTEST (L2 A-reuse)
        int f = bid - GATE_BIDS;
        mt = f / FIELD_TILES;
        nt = f - mt * FIELD_TILES;
        n_off = nt * TN;
        mode = 1;
    }

    const __half* A = g_xh + (long)mt * TM * KD;
    const __half* B = g_wt + (long)n_off * KD;

    const int wm = wid & 1, wn = wid >> 1;   // 2 x 2 warp grid
    const int m0 = wm * 64, n0 = wn * 64;

    // ldmatrix lane selectors
    const int arow = (lane & 7) + ((lane >> 3) & 1) * 8;  // 0..15 within m16
    const int ajs  = lane >> 4;                           // k-half 0/1
    const int brow = (lane & 7) + (lane >> 4) * 8;        // 0..15 within n16
    const int bjs  = (lane >> 3) & 1;                     // k-half 0/1

    Frag fr;
#pragma unroll
    for (int mi = 0; mi < 4; mi++)
        fr.row_a[mi] = (uint32_t)((m0 + mi * 16 + arow) * 128);
    fr.xor_a = (uint32_t)((arow & 7) * 16);
#pragma unroll
    for (int pi = 0; pi < 4; pi++) {
        int row = n0 + pi * 16 + brow;
        fr.row_b[pi] = (uint32_t)(row * 128);
        fr.xor_b[pi] = (uint32_t)((row & 7) * 16);
    }

    // per-thread cp.async components
    const int lr = tid >> 3, lj = tid & 7;
    const uint32_t d_pre = swz((uint32_t)(lr * 128 + lj * 16));
    const long s0 = (long)lr * KD + lj * 8;

    float c[4][8][4];
#pragma unroll
    for (int mi = 0; mi < 4; mi++)
#pragma unroll
        for (int ni = 0; ni < 8; ni++)
#pragma unroll
            for (int q = 0; q < 4; q++) c[mi][ni][q] = 0.f;

    load_stage(sb, 0, A, B, 0, tid);
    asm volatile("cp.async.commit_group;" ::: "memory");
    load_stage(sb, 1, A, B, KB, tid);
    asm volatile("cp.async.commit_group;" ::: "memory");

    // kb loop unrolled by 3 -> static stage indices
    for (int kb0 = 0; kb0 < NKB; kb0 += 3) {
#pragma unroll
        for (int u = 0; u < 3; u++) {
            const int kb = kb0 + u;
            asm volatile("cp.async.wait_group 1;" ::: "memory");
            __syncthreads();
            const bool dl = (kb + 2 < NKB);
            const __half* As = A + s0 + (long)(kb + 2) * KB;
            const __half* Bs = B + s0 + (long)(kb + 2) * KB;
            if (u == 0)
                kblock<0, 2>(sb, fr, c, ajs, bjs, d_pre, As, Bs, dl);
            else if (u == 1)
                kblock<1, 0>(sb, fr, c, ajs, bjs, d_pre, As, Bs, dl);
            else
                kblock<2, 1>(sb, fr, c, ajs, bjs, d_pre, As, Bs, dl);
            asm volatile("cp.async.commit_group;" ::: "memory");
        }
    }

    // ----- fused epilogue -----
    const long gm = (long)mt * TM + m0;
    const int rr = lane >> 2, cc = (lane & 3) * 2;

    if (mode == 0) {
        // gate columns -> sigmoid -> g_gates [NR, NGATE]
        const int gn = nt * TN + n0;
#pragma unroll
        for (int mi = 0; mi < 4; mi++)
#pragma unroll
            for (int ni = 0; ni < 8; ni++) {
                long r0 = gm + mi * 16 + rr;
                int col = gn + ni * 8 + cc;
                *reinterpret_cast<float2*>(&g_gates[r0 * NGATE + col]) =
                    make_float2(sigf(c[mi][ni][0]), sigf(c[mi][ni][1]));
                *reinterpret_cast<float2*>(&g_gates[(r0 + 8) * NGATE + col]) =
                    make_float2(sigf(c[mi][ni][2]), sigf(c[mi][ni][3]));
            }
        __syncthreads();             // all stores in the CTA done
        __threadfence();             // make them visible device-wide
        if (tid == 0) atomicAdd(&g_done[mt], 1u);
    } else {
        // wait for the 4 gate tiles of this row block (usually already done)
        if (tid == 0) {
            while (*(volatile unsigned*)&g_done[mt] < (unsigned)GATE_TILES) { }
        }
        __syncthreads();
        __threadfence();             // acquire side of the flag pattern

        // field columns -> silu / gate-mul -> out [NR, SOUT]
        const int gn = nt * TN + n0;
#pragma unroll
        for (int mi = 0; mi < 4; mi++)
#pragma unroll
            for (int ni = 0; ni < 8; ni++) {
                int col = gn + ni * 8 + cc;
                int gi0, gi1;
                if (col < 256)       { gi0 = gi1 = -1; }
                else if (col < 1024) { gi0 = (col - 256) / 3;
                                       gi1 = (col + 1 - 256) / 3; }
                else                 { gi0 = 256 + (col - 1024) / 5;
                                       gi1 = 256 + (col + 1 - 1024) / 5; }
#pragma unroll
                for (int h = 0; h < 2; h++) {
                    long r0 = gm + mi * 16 + rr + h * 8;
                    float f0 = c[mi][ni][2 * h], f1 = c[mi][ni][2 * h + 1];
                    float o0, o1;
                    if (col < 256) {
                        o0 = f0 * sigf(f0);
                        o1 = f1 * sigf(f1);
                    } else {
                        const float* grow = g_gates + r0 * NGATE;
                        o0 = f0 * grow[gi0];
                        o1 = f1 * grow[gi1];
                    }
                    *reinterpret_cast<float2*>(&out[r0 * SOUT + col]) =
                        make_float2(o0, o1);
                }
            }
    }
}

// ---------------------------------------------------------------------------
extern "C" void kernel_launch(void* const* d_in, const int* in_sizes, int n_in,
                              void* d_out, int out_size) {
    const float* x = (const float*)d_in[0];
    const float* W = (const float*)d_in[1];
    float* out = (float*)d_out;

    split_x_kernel<<<(int)((NR * KD / 4 + 255) / 256), 256>>>((const float4*)x);
    splitW_kernel<<<dim3(NF / 32, KD / 32), dim3(32, 8)>>>(W);

    cudaFuncSetAttribute(gemm_kernel,
                         cudaFuncAttributeMaxDynamicSharedMemorySize,
                         SMEM_BYTES);
    gemm_kernel<<<TOTAL_BIDS, 128, SMEM_BYTES>>>(out);
}

// round 16
// speedup vs baseline: 1.0647x; 1.0017x over previous
#include <cuda_runtime.h>
#include <cuda_fp16.h>
#include <cstdint>

// ---------------------------------------------------------------------------
// Problem constants
// ---------------------------------------------------------------------------
static constexpr long NR    = 32768;   // rows of x
static constexpr int  KD    = 2304;    // C_IN
static constexpr int  NF    = 2816;    // C_WITH_GATE
static constexpr int  SOUT  = 2304;    // SIZE_OUT
static constexpr int  NGATE = 512;     // NUM_GATES

static constexpr int TM  = 128;        // CTA tile M
static constexpr int TN  = 128;        // CTA tile N
static constexpr int KB  = 64;         // K per stage
static constexpr int NKB = KD / KB;    // 36 (divisible by 3)

static constexpr int A_BYTES = TM * KB * 2;        // 16 KB
static constexpr int STAGE   = 2 * A_BYTES;        // A + B = 32 KB
static constexpr int NSTG    = 3;
static constexpr int SMEM_BYTES = NSTG * STAGE;    // 98304 -> 2 CTAs/SM

static constexpr int MT_CNT      = (int)(NR / TM); // 256
static constexpr int GATE_TILES  = NGATE / TN;     // 4
static constexpr int FIELD_TILES = SOUT / TN;      // 18
static constexpr int GATE_BIDS   = MT_CNT * GATE_TILES;     // 1024
static constexpr int FIELD_BIDS  = MT_CNT * FIELD_TILES;    // 4608
static constexpr int TOTAL_BIDS  = GATE_BIDS + FIELD_BIDS;  // 5632

// merged prep kernel bid split
static constexpr int XPREP_BLKS  = (int)(NR * KD / 4 / 256);      // 73728
static constexpr int WPREP_BLKS  = (NF / 32) * (KD / 32);         // 6336
static constexpr int PREP_BLKS   = XPREP_BLKS + WPREP_BLKS;       // 80064

// ---------------------------------------------------------------------------
// Scratch (device globals; no runtime allocation)
// ---------------------------------------------------------------------------
__device__ __half g_xh[NR * KD];                // x in fp16
__device__ __half g_wt[(long)NF * KD];          // W^T in fp16: [NF, KD]
__device__ float  g_gates[NR * NGATE];          // sigmoid(gate feats)
__device__ unsigned g_done[MT_CNT];             // gate tiles done per mt

// ---------------------------------------------------------------------------
// Helpers (baseline compute_103: cp.async / ldmatrix / mma.sync)
// ---------------------------------------------------------------------------
__device__ __forceinline__ uint32_t smem_u32(const void* p) {
    uint32_t a;
    asm("{ .reg .u64 t; cvta.to.shared.u64 t, %1; cvt.u32.u64 %0, t; }"
        : "=r"(a) : "l"(p));
    return a;
}

__device__ __forceinline__ uint32_t swz(uint32_t o) {
    return o ^ ((o >> 3) & 0x70);   // SW128 (Swizzle<3,4,3>)
}

__device__ __forceinline__ void cp16(uint32_t dst, const void* src) {
    asm volatile("cp.async.cg.shared.global [%0], [%1], 16;"
                 :: "r"(dst), "l"(src));
}

__device__ __forceinline__ void ldsm4(uint32_t* r, uint32_t a) {
    asm volatile("ldmatrix.sync.aligned.m8n8.x4.shared.b16 {%0,%1,%2,%3}, [%4];"
                 : "=r"(r[0]), "=r"(r[1]), "=r"(r[2]), "=r"(r[3]) : "r"(a));
}

__device__ __forceinline__ void mma16816(float* c, const uint32_t* a,
                                         const uint32_t* b) {
    asm volatile(
        "mma.sync.aligned.m16n8k16.row.col.f32.f16.f16.f32 "
        "{%0,%1,%2,%3}, {%4,%5,%6,%7}, {%8,%9}, {%0,%1,%2,%3};"
        : "+f"(c[0]), "+f"(c[1]), "+f"(c[2]), "+f"(c[3])
        : "r"(a[0]), "r"(a[1]), "r"(a[2]), "r"(a[3]), "r"(b[0]), "r"(b[1]));
}

__device__ __forceinline__ float sigf(float v) {
    return 1.0f / (1.0f + __expf(-v));
}

// ---------------------------------------------------------------------------
// Kernel 1 (merged prep): x fp32->fp16 AND W transpose in ONE launch.
//   bid < XPREP_BLKS : convert 256 float4 of x   (also: block 0 resets flags)
//   else             : transpose one 32x32 tile of W
// Both halves are DRAM-streaming; running them concurrently fills the
// bandwidth split_x alone leaves idle and removes the serial splitW tail.
// ---------------------------------------------------------------------------
__global__ void prep_kernel(const float4* __restrict__ x,
                            const float* __restrict__ W) {
    const int bid = blockIdx.x;
    const int tid = threadIdx.x;

    if (bid < XPREP_BLKS) {
        if (bid == 0) g_done[tid] = 0;          // 256 threads = MT_CNT
        long i = (long)bid * 256 + tid;
        float4 v = x[i];
        __half2* p = reinterpret_cast<__half2*>(g_xh) + 2 * i;
        p[0] = __floats2half2_rn(v.x, v.y);
        p[1] = __floats2half2_rn(v.z, v.w);
        return;
    }

    __shared__ float t[32][33];
    const int wb = bid - XPREP_BLKS;
    const int n0 = (wb % (NF / 32)) * 32;
    const int k0 = (wb / (NF / 32)) * 32;
    const int tx = tid & 31, ty = tid >> 5;     // 32 x 8
#pragma unroll
    for (int i = 0; i < 32; i += 8)
        t[ty + i][tx] = W[(long)(k0 + ty + i) * NF + n0 + tx];
    __syncthreads();
#pragma unroll
    for (int i = 0; i < 32; i += 8)
        g_wt[(long)(n0 + ty + i) * KD + k0 + tx] = __float2half_rn(t[tx][ty + i]);
}

// ---------------------------------------------------------------------------
// Kernel 2: merged fp16 HMMA GEMM (gates + fields in ONE launch).
//   bid <  GATE_BIDS : gate tile  -> sigmoid -> g_gates, bump g_done[mt]
//   bid >= GATE_BIDS : field tile -> wait g_done[mt] -> silu/gate -> out
// Field tiles nt-FASTEST (L2 A-reuse). CTA 128x128, 4 warps (2x2, 64x64),
// 2 CTAs/SM, 3-stage cp.async with prefetch spread across ks groups.
// ---------------------------------------------------------------------------
__device__ __forceinline__ void load_stage(uint32_t sb, int buf,
                                           const __half* __restrict__ A,
                                           const __half* __restrict__ B,
                                           int k0, int tid) {
    const int r = tid >> 3, j = tid & 7;            // r: 0..15
    const uint32_t d0 = sb + buf * STAGE + swz((uint32_t)(r * 128 + j * 16));
    const long s0 = (long)r * KD + k0 + j * 8;
#pragma unroll
    for (int i = 0; i < 8; i++) {                   // rows r + 16*i
        uint32_t d = d0 + i * 2048;                 // +16 rows (swz invariant)
        long s = s0 + (long)i * 16 * KD;
        cp16(d, A + s);
        cp16(d + A_BYTES, B + s);
    }
}

struct Frag {
    uint32_t row_a[4];   // (row*128) for A ldsm (m16 slices)
    uint32_t xor_a;
    uint32_t row_b[4];   // (row*128) for B ldsm (n16 slices)
    uint32_t xor_b[4];
};

// One K-block on compile-time stage BUF, prefetching stage LBUF (4 cp16/ks).
template <int BUF, int LBUF>
__device__ __forceinline__ void kblock(uint32_t sb, const Frag& fr,
                                       float c[4][8][4], int ajs, int bjs,
                                       uint32_t d_pre,
                                       const __half* __restrict__ As,
                                       const __half* __restrict__ Bs,
                                       bool do_load) {
    const uint32_t baseA = sb + BUF * STAGE;
    const uint32_t baseB = baseA + A_BYTES;
    const uint32_t ld = sb + LBUF * STAGE + d_pre;
#pragma unroll
    for (int ks = 0; ks < 4; ks++) {
        const uint32_t kca = (uint32_t)((2 * ks + ajs) * 16);
        const uint32_t kcb = (uint32_t)((2 * ks + bjs) * 16);
        uint32_t a[4][4], b[4][4];
        ldsm4(b[0], baseB + fr.row_b[0] + (kcb ^ fr.xor_b[0]));
        ldsm4(a[0], baseA + fr.row_a[0] + (kca ^ fr.xor_a));
        ldsm4(b[1], baseB + fr.row_b[1] + (kcb ^ fr.xor_b[1]));
        ldsm4(a[1], baseA + fr.row_a[1] + (kca ^ fr.xor_a));
        ldsm4(b[2], baseB + fr.row_b[2] + (kcb ^ fr.xor_b[2]));
        ldsm4(a[2], baseA + fr.row_a[2] + (kca ^ fr.xor_a));
        ldsm4(b[3], baseB + fr.row_b[3] + (kcb ^ fr.xor_b[3]));
        ldsm4(a[3], baseA + fr.row_a[3] + (kca ^ fr.xor_a));
        if (do_load) {
            cp16(ld + (2 * ks) * 2048, As + (long)(2 * ks) * 16 * KD);
            cp16(ld + (2 * ks + 1) * 2048, As + (long)(2 * ks + 1) * 16 * KD);
            cp16(ld + A_BYTES + (2 * ks) * 2048,
                 Bs + (long)(2 * ks) * 16 * KD);
            cp16(ld + A_BYTES + (2 * ks + 1) * 2048,
                 Bs + (long)(2 * ks + 1) * 16 * KD);
        }
#pragma unroll
        for (int mi = 0; mi < 4; mi++)
#pragma unroll
            for (int pi = 0; pi < 4; pi++) {
                mma16816(c[mi][2 * pi],     a[mi], &b[pi][0]);
                mma16816(c[mi][2 * pi + 1], a[mi], &b[pi][2]);
            }
    }
}

__global__ void __launch_bounds__(128, 2) gemm_kernel(float* __restrict__ out) {
    extern __shared__ __align__(1024) unsigned char smem_raw[];
    const uint32_t sb = smem_u32(smem_raw);
    const int tid = threadIdx.x, lane = tid & 31, wid = tid >> 5;
    const int bid = blockIdx.x;

    int mt, nt, n_off, mode;
    if (bid < GATE_BIDS) {          // gate tiles first, nt fastest
        mt = bid >> 2;              // GATE_TILES = 4
        nt = bid & 3;
        n_off = SOUT + nt * TN;
        mode = 0;
    } else {                        // field tiles, nt FASTEST (L2 A-reuse)
        int f = bid - GATE_BIDS;
        mt = f / FIELD_TILES;
        nt = f - mt * FIELD_TILES;
        n_off = nt * TN;
        mode = 1;
    }

    const __half* A = g_xh + (long)mt * TM * KD;
    const __half* B = g_wt + (long)n_off * KD;

    const int wm = wid & 1, wn = wid >> 1;   // 2 x 2 warp grid
    const int m0 = wm * 64, n0 = wn * 64;

    // ldmatrix lane selectors
    const int arow = (lane & 7) + ((lane >> 3) & 1) * 8;  // 0..15 within m16
    const int ajs  = lane >> 4;                           // k-half 0/1
    const int brow = (lane & 7) + (lane >> 4) * 8;        // 0..15 within n16
    const int bjs  = (lane >> 3) & 1;                     // k-half 0/1

    Frag fr;
#pragma unroll
    for (int mi = 0; mi < 4; mi++)
        fr.row_a[mi] = (uint32_t)((m0 + mi * 16 + arow) * 128);
    fr.xor_a = (uint32_t)((arow & 7) * 16);
#pragma unroll
    for (int pi = 0; pi < 4; pi++) {
        int row = n0 + pi * 16 + brow;
        fr.row_b[pi] = (uint32_t)(row * 128);
        fr.xor_b[pi] = (uint32_t)((row & 7) * 16);
    }

    // per-thread cp.async components
    const int lr = tid >> 3, lj = tid & 7;
    const uint32_t d_pre = swz((uint32_t)(lr * 128 + lj * 16));
    const long s0 = (long)lr * KD + lj * 8;

    float c[4][8][4];
#pragma unroll
    for (int mi = 0; mi < 4; mi++)
#pragma unroll
        for (int ni = 0; ni < 8; ni++)
#pragma unroll
            for (int q = 0; q < 4; q++) c[mi][ni][q] = 0.f;

    load_stage(sb, 0, A, B, 0, tid);
    asm volatile("cp.async.commit_group;" ::: "memory");
    load_stage(sb, 1, A, B, KB, tid);
    asm volatile("cp.async.commit_group;" ::: "memory");

    // kb loop unrolled by 3 -> static stage indices
    for (int kb0 = 0; kb0 < NKB; kb0 += 3) {
#pragma unroll
        for (int u = 0; u < 3; u++) {
            const int kb = kb0 + u;
            asm volatile("cp.async.wait_group 1;" ::: "memory");
            __syncthreads();
            const bool dl = (kb + 2 < NKB);
            const __half* As = A + s0 + (long)(kb + 2) * KB;
            const __half* Bs = B + s0 + (long)(kb + 2) * KB;
            if (u == 0)
                kblock<0, 2>(sb, fr, c, ajs, bjs, d_pre, As, Bs, dl);
            else if (u == 1)
                kblock<1, 0>(sb, fr, c, ajs, bjs, d_pre, As, Bs, dl);
            else
                kblock<2, 1>(sb, fr, c, ajs, bjs, d_pre, As, Bs, dl);
            asm volatile("cp.async.commit_group;" ::: "memory");
        }
    }

    // ----- fused epilogue -----
    const long gm = (long)mt * TM + m0;
    const int rr = lane >> 2, cc = (lane & 3) * 2;

    if (mode == 0) {
        // gate columns -> sigmoid -> g_gates [NR, NGATE]
        const int gn = nt * TN + n0;
#pragma unroll
        for (int mi = 0; mi < 4; mi++)
#pragma unroll
            for (int ni = 0; ni < 8; ni++) {
                long r0 = gm + mi * 16 + rr;
                int col = gn + ni * 8 + cc;
                *reinterpret_cast<float2*>(&g_gates[r0 * NGATE + col]) =
                    make_float2(sigf(c[mi][ni][0]), sigf(c[mi][ni][1]));
                *reinterpret_cast<float2*>(&g_gates[(r0 + 8) * NGATE + col]) =
                    make_float2(sigf(c[mi][ni][2]), sigf(c[mi][ni][3]));
            }
        __syncthreads();             // all stores in the CTA done
        __threadfence();             // make them visible device-wide
        if (tid == 0) atomicAdd(&g_done[mt], 1u);
    } else {
        // wait for the 4 gate tiles of this row block (usually already done)
        if (tid == 0) {
            while (*(volatile unsigned*)&g_done[mt] < (unsigned)GATE_TILES) { }
        }
        __syncthreads();
        __threadfence();             // acquire side of the flag pattern

        // field columns -> silu / gate-mul -> out [NR, SOUT]
        const int gn = nt * TN + n0;
#pragma unroll
        for (int mi = 0; mi < 4; mi++)
#pragma unroll
            for (int ni = 0; ni < 8; ni++) {
                int col = gn + ni * 8 + cc;
                int gi0, gi1;
                if (col < 256)       { gi0 = gi1 = -1; }
                else if (col < 1024) { gi0 = (col - 256) / 3;
                                       gi1 = (col + 1 - 256) / 3; }
                else                 { gi0 = 256 + (col - 1024) / 5;
                                       gi1 = 256 + (col + 1 - 1024) / 5; }
#pragma unroll
                for (int h = 0; h < 2; h++) {
                    long r0 = gm + mi * 16 + rr + h * 8;
                    float f0 = c[mi][ni][2 * h], f1 = c[mi][ni][2 * h + 1];
                    float o0, o1;
                    if (col < 256) {
                        o0 = f0 * sigf(f0);
                        o1 = f1 * sigf(f1);
                    } else {
                        const float* grow = g_gates + r0 * NGATE;
                        o0 = f0 * grow[gi0];
                        o1 = f1 * grow[gi1];
                    }
                    *reinterpret_cast<float2*>(&out[r0 * SOUT + col]) =
                        make_float2(o0, o1);
                }
            }
    }
}

// ---------------------------------------------------------------------------
extern "C" void kernel_launch(void* const* d_in, const int* in_sizes, int n_in,
                              void* d_out, int out_size) {
    const float* x = (const float*)d_in[0];
    const float* W = (const float*)d_in[1];
    float* out = (float*)d_out;

    prep_kernel<<<PREP_BLKS, 256>>>((const float4*)x, W);

    cudaFuncSetAttribute(gemm_kernel,
                         cudaFuncAttributeMaxDynamicSharedMemorySize,
                         SMEM_BYTES);
    gemm_kernel<<<TOTAL_BIDS, 128, SMEM_BYTES>>>(out);
}

// round 17
// speedup vs baseline: 1.0774x; 1.0119x over previous
#include <cuda_runtime.h>
#include <cuda_fp16.h>
#include <cstdint>

// ---------------------------------------------------------------------------
// Problem constants
// ---------------------------------------------------------------------------
static constexpr long NR    = 32768;   // rows of x
static constexpr int  KD    = 2304;    // C_IN
static constexpr int  NF    = 2816;    // C_WITH_GATE
static constexpr int  SOUT  = 2304;    // SIZE_OUT
static constexpr int  NGATE = 512;     // NUM_GATES

static constexpr int TM  = 128;        // CTA tile M
static constexpr int TN  = 128;        // CTA tile N
static constexpr int KB  = 64;         // K per stage
static constexpr int NKB = KD / KB;    // 36 (divisible by 3)

static constexpr int A_BYTES = TM * KB * 2;        // 16 KB
static constexpr int STAGE   = 2 * A_BYTES;        // A + B = 32 KB
static constexpr int NSTG    = 3;
static constexpr int SMEM_BYTES = NSTG * STAGE;    // 98304 -> 2 CTAs/SM

static constexpr int MT_CNT      = (int)(NR / TM); // 256
static constexpr int GATE_TILES  = NGATE / TN;     // 4
static constexpr int FIELD_TILES = SOUT / TN;      // 18
static constexpr int GATE_BIDS   = MT_CNT * GATE_TILES;     // 1024
static constexpr int FIELD_BIDS  = MT_CNT * FIELD_TILES;    // 4608
static constexpr int TOTAL_BIDS  = GATE_BIDS + FIELD_BIDS;  // 5632

// merged prep kernel bid split (x blocks process 1024 float4 each, MLP=4)
static constexpr int XPREP_BLKS  = (int)(NR * KD / 4 / 1024);     // 18432
static constexpr int WPREP_BLKS  = (NF / 32) * (KD / 32);         // 6336
static constexpr int PREP_BLKS   = XPREP_BLKS + WPREP_BLKS;       // 24768

// ---------------------------------------------------------------------------
// Scratch (device globals; no runtime allocation)
// ---------------------------------------------------------------------------
__device__ __half g_xh[NR * KD];                // x in fp16
__device__ __half g_wt[(long)NF * KD];          // W^T in fp16: [NF, KD]
__device__ float  g_gates[NR * NGATE];          // sigmoid(gate feats)
__device__ unsigned g_done[MT_CNT];             // gate tiles done per mt

// ---------------------------------------------------------------------------
// Helpers (baseline compute_103: cp.async / ldmatrix / mma.sync)
// ---------------------------------------------------------------------------
__device__ __forceinline__ uint32_t smem_u32(const void* p) {
    uint32_t a;
    asm("{ .reg .u64 t; cvta.to.shared.u64 t, %1; cvt.u32.u64 %0, t; }"
        : "=r"(a) : "l"(p));
    return a;
}

__device__ __forceinline__ uint32_t swz(uint32_t o) {
    return o ^ ((o >> 3) & 0x70);   // SW128 (Swizzle<3,4,3>)
}

__device__ __forceinline__ void cp16(uint32_t dst, const void* src) {
    asm volatile("cp.async.cg.shared.global [%0], [%1], 16;"
                 :: "r"(dst), "l"(src));
}

__device__ __forceinline__ void ldsm4(uint32_t* r, uint32_t a) {
    asm volatile("ldmatrix.sync.aligned.m8n8.x4.shared.b16 {%0,%1,%2,%3}, [%4];"
                 : "=r"(r[0]), "=r"(r[1]), "=r"(r[2]), "=r"(r[3]) : "r"(a));
}

__device__ __forceinline__ void mma16816(float* c, const uint32_t* a,
                                         const uint32_t* b) {
    asm volatile(
        "mma.sync.aligned.m16n8k16.row.col.f32.f16.f16.f32 "
        "{%0,%1,%2,%3}, {%4,%5,%6,%7}, {%8,%9}, {%0,%1,%2,%3};"
        : "+f"(c[0]), "+f"(c[1]), "+f"(c[2]), "+f"(c[3])
        : "r"(a[0]), "r"(a[1]), "r"(a[2]), "r"(a[3]), "r"(b[0]), "r"(b[1]));
}

__device__ __forceinline__ float sigf(float v) {
    return 1.0f / (1.0f + __expf(-v));
}

// ---------------------------------------------------------------------------
// Kernel 1 (merged prep): x fp32->fp16 AND W transpose in ONE launch.
//   bid < XPREP_BLKS : convert 1024 float4 of x, 4 per thread with batched
//                      independent loads (MLP=4 -> hides DRAM latency)
//   else             : transpose one 32x32 tile of W
// ---------------------------------------------------------------------------
__global__ void prep_kernel(const float4* __restrict__ x,
                            const float* __restrict__ W) {
    const int bid = blockIdx.x;
    const int tid = threadIdx.x;

    if (bid < XPREP_BLKS) {
        if (bid == 0) g_done[tid] = 0;          // 256 threads = MT_CNT
        const long base = (long)bid * 1024 + tid;
        // 4 independent loads first (MLP=4), then convert + store
        float4 v0 = x[base];
        float4 v1 = x[base + 256];
        float4 v2 = x[base + 512];
        float4 v3 = x[base + 768];
        __half2* p = reinterpret_cast<__half2*>(g_xh);
        p[2 * base]              = __floats2half2_rn(v0.x, v0.y);
        p[2 * base + 1]          = __floats2half2_rn(v0.z, v0.w);
        p[2 * (base + 256)]      = __floats2half2_rn(v1.x, v1.y);
        p[2 * (base + 256) + 1]  = __floats2half2_rn(v1.z, v1.w);
        p[2 * (base + 512)]      = __floats2half2_rn(v2.x, v2.y);
        p[2 * (base + 512) + 1]  = __floats2half2_rn(v2.z, v2.w);
        p[2 * (base + 768)]      = __floats2half2_rn(v3.x, v3.y);
        p[2 * (base + 768) + 1]  = __floats2half2_rn(v3.z, v3.w);
        return;
    }

    __shared__ float t[32][33];
    const int wb = bid - XPREP_BLKS;
    const int n0 = (wb % (NF / 32)) * 32;
    const int k0 = (wb / (NF / 32)) * 32;
    const int tx = tid & 31, ty = tid >> 5;     // 32 x 8
#pragma unroll
    for (int i = 0; i < 32; i += 8)
        t[ty + i][tx] = W[(long)(k0 + ty + i) * NF + n0 + tx];
    __syncthreads();
#pragma unroll
    for (int i = 0; i < 32; i += 8)
        g_wt[(long)(n0 + ty + i) * KD + k0 + tx] = __float2half_rn(t[tx][ty + i]);
}

// ---------------------------------------------------------------------------
// Kernel 2: merged fp16 HMMA GEMM (gates + fields in ONE launch).
//   bid <  GATE_BIDS : gate tile  -> sigmoid -> g_gates, bump g_done[mt]
//   bid >= GATE_BIDS : field tile -> wait g_done[mt] -> silu/gate -> out
// Field tiles nt-FASTEST (L2 A-reuse). CTA 128x128, 4 warps (2x2, 64x64),
// 2 CTAs/SM, 3-stage cp.async with prefetch spread across ks groups.
// ---------------------------------------------------------------------------
__device__ __forceinline__ void load_stage(uint32_t sb, int buf,
                                           const __half* __restrict__ A,
                                           const __half* __restrict__ B,
                                           int k0, int tid) {
    const int r = tid >> 3, j = tid & 7;            // r: 0..15
    const uint32_t d0 = sb + buf * STAGE + swz((uint32_t)(r * 128 + j * 16));
    const long s0 = (long)r * KD + k0 + j * 8;
#pragma unroll
    for (int i = 0; i < 8; i++) {                   // rows r + 16*i
        uint32_t d = d0 + i * 2048;                 // +16 rows (swz invariant)
        long s = s0 + (long)i * 16 * KD;
        cp16(d, A + s);
        cp16(d + A_BYTES, B + s);
    }
}

struct Frag {
    uint32_t row_a[4];   // (row*128) for A ldsm (m16 slices)
    uint32_t xor_a;
    uint32_t row_b[4];   // (row*128) for B ldsm (n16 slices)
    uint32_t xor_b[4];
};

// One K-block on compile-time stage BUF, prefetching stage LBUF (4 cp16/ks).
template <int BUF, int LBUF>
__device__ __forceinline__ void kblock(uint32_t sb, const Frag& fr,
                                       float c[4][8][4], int ajs, int bjs,
                                       uint32_t d_pre,
                                       const __half* __restrict__ As,
                                       const __half* __restrict__ Bs,
                                       bool do_load) {
    const uint32_t baseA = sb + BUF * STAGE;
    const uint32_t baseB = baseA + A_BYTES;
    const uint32_t ld = sb + LBUF * STAGE + d_pre;
#pragma unroll
    for (int ks = 0; ks < 4; ks++) {
        const uint32_t kca = (uint32_t)((2 * ks + ajs) * 16);
        const uint32_t kcb = (uint32_t)((2 * ks + bjs) * 16);
        uint32_t a[4][4], b[4][4];
        ldsm4(b[0], baseB + fr.row_b[0] + (kcb ^ fr.xor_b[0]));
        ldsm4(a[0], baseA + fr.row_a[0] + (kca ^ fr.xor_a));
        ldsm4(b[1], baseB + fr.row_b[1] + (kcb ^ fr.xor_b[1]));
        ldsm4(a[1], baseA + fr.row_a[1] + (kca ^ fr.xor_a));
        ldsm4(b[2], baseB + fr.row_b[2] + (kcb ^ fr.xor_b[2]));
        ldsm4(a[2], baseA + fr.row_a[2] + (kca ^ fr.xor_a));
        ldsm4(b[3], baseB + fr.row_b[3] + (kcb ^ fr.xor_b[3]));
        ldsm4(a[3], baseA + fr.row_a[3] + (kca ^ fr.xor_a));
        if (do_load) {
            cp16(ld + (2 * ks) * 2048, As + (long)(2 * ks) * 16 * KD);
            cp16(ld + (2 * ks + 1) * 2048, As + (long)(2 * ks + 1) * 16 * KD);
            cp16(ld + A_BYTES + (2 * ks) * 2048,
                 Bs + (long)(2 * ks) * 16 * KD);
            cp16(ld + A_BYTES + (2 * ks + 1) * 2048,
                 Bs + (long)(2 * ks + 1) * 16 * KD);
        }
#pragma unroll
        for (int mi = 0; mi < 4; mi++)
#pragma unroll
            for (int pi = 0; pi < 4; pi++) {
                mma16816(c[mi][2 * pi],     a[mi], &b[pi][0]);
                mma16816(c[mi][2 * pi + 1], a[mi], &b[pi][2]);
            }
    }
}

__global__ void __launch_bounds__(128, 2) gemm_kernel(float* __restrict__ out) {
    extern __shared__ __align__(1024) unsigned char smem_raw[];
    const uint32_t sb = smem_u32(smem_raw);
    const int tid = threadIdx.x, lane = tid & 31, wid = tid >> 5;
    const int bid = blockIdx.x;

    int mt, nt, n_off, mode;
    if (bid < GATE_BIDS) {          // gate tiles first, nt fastest
        mt = bid >> 2;              // GATE_TILES = 4
        nt = bid & 3;
        n_off = SOUT + nt * TN;
        mode = 0;
    } else {                        // field tiles, nt FASTEST (L2 A-reuse)
        int f = bid - GATE_BIDS;
        mt = f / FIELD_TILES;
        nt = f - mt * FIELD_TILES;
        n_off = nt * TN;
        mode = 1;
    }

    const __half* A = g_xh + (long)mt * TM * KD;
    const __half* B = g_wt + (long)n_off * KD;

    const int wm = wid & 1, wn = wid >> 1;   // 2 x 2 warp grid
    const int m0 = wm * 64, n0 = wn * 64;

    // ldmatrix lane selectors
    const int arow = (lane & 7) + ((lane >> 3) & 1) * 8;  // 0..15 within m16
    const int ajs  = lane >> 4;                           // k-half 0/1
    const int brow = (lane & 7) + (lane >> 4) * 8;        // 0..15 within n16
    const int bjs  = (lane >> 3) & 1;                     // k-half 0/1

    Frag fr;
#pragma unroll
    for (int mi = 0; mi < 4; mi++)
        fr.row_a[mi] = (uint32_t)((m0 + mi * 16 + arow) * 128);
    fr.xor_a = (uint32_t)((arow & 7) * 16);
#pragma unroll
    for (int pi = 0; pi < 4; pi++) {
        int row = n0 + pi * 16 + brow;
        fr.row_b[pi] = (uint32_t)(row * 128);
        fr.xor_b[pi] = (uint32_t)((row & 7) * 16);
    }

    // per-thread cp.async components
    const int lr = tid >> 3, lj = tid & 7;
    const uint32_t d_pre = swz((uint32_t)(lr * 128 + lj * 16));
    const long s0 = (long)lr * KD + lj * 8;

    float c[4][8][4];
#pragma unroll
    for (int mi = 0; mi < 4; mi++)
#pragma unroll
        for (int ni = 0; ni < 8; ni++)
#pragma unroll
            for (int q = 0; q < 4; q++) c[mi][ni][q] = 0.f;

    load_stage(sb, 0, A, B, 0, tid);
    asm volatile("cp.async.commit_group;" ::: "memory");
    load_stage(sb, 1, A, B, KB, tid);
    asm volatile("cp.async.commit_group;" ::: "memory");

    // kb loop unrolled by 3 -> static stage indices
    for (int kb0 = 0; kb0 < NKB; kb0 += 3) {
#pragma unroll
        for (int u = 0; u < 3; u++) {
            const int kb = kb0 + u;
            asm volatile("cp.async.wait_group 1;" ::: "memory");
            __syncthreads();
            const bool dl = (kb + 2 < NKB);
            const __half* As = A + s0 + (long)(kb + 2) * KB;
            const __half* Bs = B + s0 + (long)(kb + 2) * KB;
            if (u == 0)
                kblock<0, 2>(sb, fr, c, ajs, bjs, d_pre, As, Bs, dl);
            else if (u == 1)
                kblock<1, 0>(sb, fr, c, ajs, bjs, d_pre, As, Bs, dl);
            else
                kblock<2, 1>(sb, fr, c, ajs, bjs, d_pre, As, Bs, dl);
            asm volatile("cp.async.commit_group;" ::: "memory");
        }
    }

    // ----- fused epilogue -----
    const long gm = (long)mt * TM + m0;
    const int rr = lane >> 2, cc = (lane & 3) * 2;

    if (mode == 0) {
        // gate columns -> sigmoid -> g_gates [NR, NGATE]
        const int gn = nt * TN + n0;
#pragma unroll
        for (int mi = 0; mi < 4; mi++)
#pragma unroll
            for (int ni = 0; ni < 8; ni++) {
                long r0 = gm + mi * 16 + rr;
                int col = gn + ni * 8 + cc;
                *reinterpret_cast<float2*>(&g_gates[r0 * NGATE + col]) =
                    make_float2(sigf(c[mi][ni][0]), sigf(c[mi][ni][1]));
                *reinterpret_cast<float2*>(&g_gates[(r0 + 8) * NGATE + col]) =
                    make_float2(sigf(c[mi][ni][2]), sigf(c[mi][ni][3]));
            }
        __syncthreads();             // all stores in the CTA done
        __threadfence();             // make them visible device-wide
        if (tid == 0) atomicAdd(&g_done[mt], 1u);
    } else {
        // wait for the 4 gate tiles of this row block (usually already done)
        if (tid == 0) {
            while (*(volatile unsigned*)&g_done[mt] < (unsigned)GATE_TILES) { }
        }
        __syncthreads();
        __threadfence();             // acquire side of the flag pattern

        // field columns -> silu / gate-mul -> out [NR, SOUT]
        const int gn = nt * TN + n0;
#pragma unroll
        for (int mi = 0; mi < 4; mi++)
#pragma unroll
            for (int ni = 0; ni < 8; ni++) {
                int col = gn + ni * 8 + cc;
                int gi0, gi1;
                if (col < 256)       { gi0 = gi1 = -1; }
                else if (col < 1024) { gi0 = (col - 256) / 3;
                                       gi1 = (col + 1 - 256) / 3; }
                else                 { gi0 = 256 + (col - 1024) / 5;
                                       gi1 = 256 + (col + 1 - 1024) / 5; }
#pragma unroll
                for (int h = 0; h < 2; h++) {
                    long r0 = gm + mi * 16 + rr + h * 8;
                    float f0 = c[mi][ni][2 * h], f1 = c[mi][ni][2 * h + 1];
                    float o0, o1;
                    if (col < 256) {
                        o0 = f0 * sigf(f0);
                        o1 = f1 * sigf(f1);
                    } else {
                        const float* grow = g_gates + r0 * NGATE;
                        o0 = f0 * grow[gi0];
                        o1 = f1 * grow[gi1];
                    }
                    *reinterpret_cast<float2*>(&out[r0 * SOUT + col]) =
                        make_float2(o0, o1);
                }
            }
    }
}

// ---------------------------------------------------------------------------
extern "C" void kernel_launch(void* const* d_in, const int* in_sizes, int n_in,
                              void* d_out, int out_size) {
    const float* x = (const float*)d_in[0];
    const float* W = (const float*)d_in[1];
    float* out = (float*)d_out;

    prep_kernel<<<PREP_BLKS, 256>>>((const float4*)x, W);

    cudaFuncSetAttribute(gemm_kernel,
                         cudaFuncAttributeMaxDynamicSharedMemorySize,
                         SMEM_BYTES);
    gemm_kernel<<<TOTAL_BIDS, 128, SMEM_BYTES>>>(out);
}